// round 14
// baseline (speedup 1.0000x reference)
#include <cuda_runtime.h>
#include <cuda_fp16.h>
#include <mma.h>
#include <cstdint>

using namespace nvcuda;

#define NODES_MAX 50000
#define PAD_M     50176      // 392*128, pad for unguarded wmma stores
#define E_MAX     1000000
#define IN_C  256
#define HID_C 128
#define OUT_C 64

#define SCAN_B    196        // scan blocks: 196*256 = 50176 >= NODES_MAX
#define ZN        (NODES_MAX + 1 + SCAN_B)   // deg | ticket | scan state

#define FPAD 136             // fused2 A smem row stride (halves)
#define BPAD 72              // fused2 B smem row stride (halves)
#define FUSED2_SMEM (128 * FPAD * 2 + 128 * BPAD * 2)   // 53248 bytes

// ---------------- scratch ----------------------------------------------------
__device__ __half g_w1h[IN_C * HID_C];       // W1, fp16
__device__ __half g_w2h[HID_C * OUT_C];      // W2, fp16
__device__ __half g_f1h[PAD_M * HID_C];      // gemm1 output (X@W1), fp16 messages
__device__ __half g_f2h[PAD_M * OUT_C];      // fused2 output, fp16 messages
__device__ float  g_dinv[NODES_MAX];
__device__ int    g_zero[ZN];                // [0,M)=deg, [NODES_MAX]=ticket,
                                             // [NODES_MAX+1,+SCAN_B)=scan state
__device__ int    g_row_start[NODES_MAX + 1];
__device__ int    g_cursor[NODES_MAX];
__device__ int    g_src[E_MAX];              // CSR-by-dst: source node per slot
__device__ int    g_is64;

__global__ void fused2_kernel(const float* __restrict__ b1, int M);

// ---------------- side stream / events / symbol addr (static init) ----------
namespace {
struct SideStream {
    cudaStream_t s2 = nullptr;
    cudaEvent_t  ev_fork = nullptr, ev_det = nullptr, ev_join = nullptr;
    void* zero_ptr = nullptr;
    SideStream() {
        cudaStreamCreateWithFlags(&s2, cudaStreamNonBlocking);
        cudaEventCreateWithFlags(&ev_fork, cudaEventDisableTiming);
        cudaEventCreateWithFlags(&ev_det,  cudaEventDisableTiming);
        cudaEventCreateWithFlags(&ev_join, cudaEventDisableTiming);
        cudaGetSymbolAddress(&zero_ptr, g_zero);
        cudaFuncSetAttribute(fused2_kernel,
                             cudaFuncAttributeMaxDynamicSharedMemorySize,
                             FUSED2_SMEM);
    }
};
SideStream g_ss;
}

// ---------------- cp.async helpers ------------------------------------------
__device__ __forceinline__ void cp16(void* smem, const void* gsrc, int szbytes) {
    uint32_t sa = (uint32_t)__cvta_generic_to_shared(smem);
    asm volatile("cp.async.cg.shared.global [%0], [%1], 16, %2;"
                 :: "r"(sa), "l"(gsrc), "r"(szbytes));
}
#define CP_COMMIT()  asm volatile("cp.async.commit_group;" ::: "memory")
#define CP_WAIT0()   asm volatile("cp.async.wait_group 0;" ::: "memory")

// ---------------- weight convert + dtype detect (fused, side stream) --------
// Blocks [0, gridDim-2): convert W1/W2 fp32->fp16.  Last block: detect.
__global__ __launch_bounds__(256) void convert_w_kernel(
    const float* __restrict__ W1, const float* __restrict__ W2,
    const long long* __restrict__ ei, int E, int M) {
    if ((int)blockIdx.x == (int)gridDim.x - 1) {
        __shared__ int bad;
        if (threadIdx.x == 0) bad = 0;
        __syncthreads();
        if ((int)threadIdx.x < E) {
            long long v = ei[threadIdx.x];
            if (v < 0 || v >= (long long)M) bad = 1;
        }
        __syncthreads();
        if (threadIdx.x == 0) g_is64 = bad ? 0 : 1;
        return;
    }
    int i = blockIdx.x * blockDim.x + threadIdx.x;
    int nw1 = IN_C * HID_C / 8;
    int nw2 = HID_C * OUT_C / 8;
    const float* src; __half* dst; int base;
    if (i < nw1)            { src = W1; dst = g_w1h; base = i; }
    else if (i < nw1 + nw2) { src = W2; dst = g_w2h; base = i - nw1; }
    else return;
    float4 a = ((const float4*)src)[base * 2];
    float4 b = ((const float4*)src)[base * 2 + 1];
    __half2 h0 = __floats2half2_rn(a.x, a.y);
    __half2 h1 = __floats2half2_rn(a.z, a.w);
    __half2 h2 = __floats2half2_rn(b.x, b.y);
    __half2 h3 = __floats2half2_rn(b.z, b.w);
    uint4 u;
    u.x = *(uint32_t*)&h0; u.y = *(uint32_t*)&h1;
    u.z = *(uint32_t*)&h2; u.w = *(uint32_t*)&h3;
    ((uint4*)dst)[base] = u;
}

// ---------------- edge loaders (4 edges/thread, vectorized) -----------------
__device__ __forceinline__ void load_dst4(const void* ei, int E, int e0, int is64,
                                          int n, int (&d)[4]) {
    if (is64) {
        const long long* p = (const long long*)ei + E + e0;
        if (n == 4) {
            longlong2 a = *(const longlong2*)p;
            longlong2 b = *(const longlong2*)(p + 2);
            d[0] = (int)a.x; d[1] = (int)a.y; d[2] = (int)b.x; d[3] = (int)b.y;
        } else {
            for (int k = 0; k < n; ++k) d[k] = (int)p[k];
        }
    } else {
        const int* p = (const int*)ei + E + e0;
        if (n == 4) {
            int4 a = *(const int4*)p;
            d[0] = a.x; d[1] = a.y; d[2] = a.z; d[3] = a.w;
        } else {
            for (int k = 0; k < n; ++k) d[k] = p[k];
        }
    }
}

__device__ __forceinline__ void load_src4(const void* ei, int e0, int is64,
                                          int n, int (&s)[4]) {
    if (is64) {
        const long long* p = (const long long*)ei + e0;
        if (n == 4) {
            longlong2 a = *(const longlong2*)p;
            longlong2 b = *(const longlong2*)(p + 2);
            s[0] = (int)a.x; s[1] = (int)a.y; s[2] = (int)b.x; s[3] = (int)b.y;
        } else {
            for (int k = 0; k < n; ++k) s[k] = (int)p[k];
        }
    } else {
        const int* p = (const int*)ei + e0;
        if (n == 4) {
            int4 a = *(const int4*)p;
            s[0] = a.x; s[1] = a.y; s[2] = a.z; s[3] = a.w;
        } else {
            for (int k = 0; k < n; ++k) s[k] = p[k];
        }
    }
}

// dst-only degree count, 4 edges/thread
__global__ void count_deg_kernel(const void* __restrict__ ei, int E) {
    int e0 = (blockIdx.x * blockDim.x + threadIdx.x) * 4;
    if (e0 >= E) return;
    int n = min(4, E - e0);
    int d[4];
    load_dst4(ei, E, e0, g_is64, n, d);
    #pragma unroll
    for (int k = 0; k < 4; ++k)
        if (k < n) atomicAdd(&g_zero[d[k]], 1);
}

// ---------------- single-kernel scan, warp-parallel lookback ----------------
__global__ __launch_bounds__(256) void scan_kernel(int M, int E) {
    __shared__ int bid_s;
    __shared__ int wsum[8];
    __shared__ int base_s;
    int t = threadIdx.x;
    if (t == 0) bid_s = atomicAdd(&g_zero[NODES_MAX], 1);
    __syncthreads();
    int bid = bid_s;
    int i = bid * 256 + t;
    int d = (i < M) ? g_zero[i] : 0;
    if (i < M) g_dinv[i] = rsqrtf((float)(d + 1));   // +1 self loop

    int lane = t & 31, wid = t >> 5;
    int v = d;
    #pragma unroll
    for (int off = 1; off < 32; off <<= 1) {
        int u = __shfl_up_sync(0xffffffffu, v, off);
        if (lane >= off) v += u;
    }
    if (lane == 31) wsum[wid] = v;
    __syncthreads();
    if (t < 8) {
        int s = wsum[t];
        #pragma unroll
        for (int off = 1; off < 8; off <<= 1) {
            int u = __shfl_up_sync(0xffu, s, off);
            if ((int)t >= off) s += u;
        }
        wsum[t] = s;
    }
    __syncthreads();
    int incl  = v + ((wid > 0) ? wsum[wid - 1] : 0);
    int total = wsum[7];

    int* state = &g_zero[NODES_MAX + 1];
    if (wid == 0) {
        if (bid == 0) {
            if (lane == 0) {
                atomicExch(&state[0], (int)((2u << 30) | (unsigned)total));
                base_s = 0;
            }
        } else {
            if (lane == 0)
                atomicExch(&state[bid], (int)((1u << 30) | (unsigned)total));
            int run = 0;
            int wstart = bid - 1;
            for (;;) {
                int j = wstart - lane;
                bool active = (j >= 0);
                unsigned s = 0;
                do {
                    if (active) s = (unsigned)atomicAdd(&state[j], 0);
                } while (__any_sync(0xffffffffu, active && (s >> 30) == 0u));
                unsigned incl_mask =
                    __ballot_sync(0xffffffffu, active && (s >> 30) == 2u);
                if (incl_mask) {
                    int L = __ffs(incl_mask) - 1;
                    int contrib = (active && lane <= L) ? (int)(s & 0x3FFFFFFFu) : 0;
                    run += __reduce_add_sync(0xffffffffu, contrib);
                    break;
                } else {
                    int contrib = active ? (int)(s & 0x3FFFFFFFu) : 0;
                    run += __reduce_add_sync(0xffffffffu, contrib);
                    wstart -= 32;
                    if (wstart < 0) break;
                }
            }
            if (lane == 0) {
                base_s = run;
                atomicExch(&state[bid], (int)((2u << 30) | (unsigned)(run + total)));
            }
        }
    }
    __syncthreads();
    int rs = base_s + incl - d;
    if (i < M) {
        g_row_start[i] = rs;
        g_cursor[i]    = rs;
    }
    if (i == M - 1) g_row_start[M] = E;
}

// CSR fill, 4 edges/thread
__global__ void fill_kernel(const void* __restrict__ ei, int E) {
    int e0 = (blockIdx.x * blockDim.x + threadIdx.x) * 4;
    if (e0 >= E) return;
    int n = min(4, E - e0);
    int s[4], d[4];
    load_src4(ei, e0, g_is64, n, s);
    load_dst4(ei, E, e0, g_is64, n, d);
    #pragma unroll
    for (int k = 0; k < 4; ++k) {
        if (k < n) {
            int pos = atomicAdd(&g_cursor[d[k]], 1);
            g_src[pos] = s[k];
        }
    }
}

// ---------------- GEMM1 (fp16 HMMA, inline X conversion): f1h = fp16(X)@W1h -
#define NT1 (IN_C / 32)
__global__ __launch_bounds__(256, 2) void gemm1_kernel(
    const float* __restrict__ X, int M) {
    __shared__ union {
        struct { __half As[2][128][40]; __half Bs[2][32][136]; } p;
        float stage[128 * 64];
    } sm;
    int tid = threadIdx.x;
    int wid = tid >> 5;
    int wm = wid & 3;
    int wn = wid >> 2;
    int bm = blockIdx.x * 128;

    wmma::fragment<wmma::accumulator, 16, 16, 16, float> c[2][4];
    #pragma unroll
    for (int i = 0; i < 2; i++)
        #pragma unroll
        for (int j = 0; j < 4; j++) wmma::fill_fragment(c[i][j], 0.f);

    float4 rg[4];
    auto ldA = [&](int kt) {
        int k0 = kt * 32;
        #pragma unroll
        for (int i = 0; i < 4; ++i) {
            int idx = tid * 4 + i;
            int r = idx >> 3, c4 = (idx & 7) * 4;
            int gm = bm + r;
            rg[i] = make_float4(0.f, 0.f, 0.f, 0.f);
            if (gm < M) rg[i] = *(const float4*)&X[(size_t)gm * IN_C + k0 + c4];
        }
    };
    auto stA = [&](int buf) {
        #pragma unroll
        for (int i = 0; i < 4; ++i) {
            int idx = tid * 4 + i;
            int r = idx >> 3, c4 = (idx & 7) * 4;
            __half2 h0 = __floats2half2_rn(rg[i].x, rg[i].y);
            __half2 h1 = __floats2half2_rn(rg[i].z, rg[i].w);
            uint2 u;
            u.x = *(uint32_t*)&h0; u.y = *(uint32_t*)&h1;
            *(uint2*)&sm.p.As[buf][r][c4] = u;
        }
    };
    auto issueB = [&](int kt, int buf) {
        int k0 = kt * 32;
        #pragma unroll
        for (int i = 0; i < 2; ++i) {
            int idx = tid * 2 + i;
            int kk = idx >> 4, n8 = (idx & 15) * 8;
            cp16(&sm.p.Bs[buf][kk][n8], &g_w1h[(size_t)(k0 + kk) * HID_C + n8], 16);
        }
        CP_COMMIT();
    };
    auto compute = [&](int buf) {
        #pragma unroll
        for (int ks = 0; ks < 32; ks += 16) {
            wmma::fragment<wmma::matrix_a, 16, 16, 16, __half, wmma::row_major> a[2];
            wmma::fragment<wmma::matrix_b, 16, 16, 16, __half, wmma::row_major> b[4];
            #pragma unroll
            for (int i = 0; i < 2; i++)
                wmma::load_matrix_sync(a[i], &sm.p.As[buf][wm * 32 + i * 16][ks], 40);
            #pragma unroll
            for (int j = 0; j < 4; j++)
                wmma::load_matrix_sync(b[j], &sm.p.Bs[buf][ks][wn * 64 + j * 16], 136);
            #pragma unroll
            for (int i = 0; i < 2; i++)
                #pragma unroll
                for (int j = 0; j < 4; j++)
                    wmma::mma_sync(c[i][j], a[i], b[j], c[i][j]);
        }
    };

    ldA(0); issueB(0, 0);
    stA(0); CP_WAIT0(); __syncthreads();
    for (int t = 0; t < NT1; ++t) {
        bool more = (t + 1 < NT1);
        if (more) { ldA(t + 1); issueB(t + 1, (t + 1) & 1); }
        compute(t & 1);
        if (more) { stA((t + 1) & 1); CP_WAIT0(); }
        __syncthreads();
    }

    #pragma unroll
    for (int half = 0; half < 2; ++half) {
        if (wn == half) {
            #pragma unroll
            for (int i = 0; i < 2; i++)
                #pragma unroll
                for (int j = 0; j < 4; j++)
                    wmma::store_matrix_sync(&sm.stage[(wm * 32 + i * 16) * 64 + j * 16],
                                            c[i][j], 64, wmma::mem_row_major);
        }
        __syncthreads();
        #pragma unroll
        for (int it = 0; it < 16; ++it) {
            int idx = tid + it * 256;
            int r  = idx >> 5;
            int cp = idx & 31;
            int gm = bm + r;
            if (gm < M) {
                float2 f = *(float2*)&sm.stage[r * 64 + cp * 2];
                *(__half2*)&g_f1h[(size_t)gm * HID_C + half * 64 + cp * 2] =
                    __float22half2_rn(f);
            }
        }
        __syncthreads();
    }
}

// ---------------- FUSED: gather1 (+b1, relu) -> smem -> GEMM2 -> f2h --------
__global__ __launch_bounds__(256) void fused2_kernel(const float* __restrict__ b1, int M) {
    extern __shared__ char dyn_sm[];
    __half* As   = (__half*)dyn_sm;                       // [128][FPAD]
    __half* Bsm  = (__half*)(dyn_sm + 128 * FPAD * 2);    // [128][BPAD]
    float*  stage = (float*)dyn_sm;                       // overlaps As (after GEMM)

    int tid  = threadIdx.x;
    int wid  = tid >> 5;
    int lane = tid & 31;
    int bm   = blockIdx.x * 128;

    // Prefetch full W2 (128x64 fp16) via cp.async while gathering.
    #pragma unroll
    for (int i = 0; i < 4; ++i) {
        int cidx = tid + i * 256;
        int row  = cidx >> 3;
        int off8 = (cidx & 7) * 8;
        cp16(&Bsm[row * BPAD + off8], &g_w2h[row * OUT_C + off8], 16);
    }
    CP_COMMIT();

    float4 bb = __ldg((const float4*)b1 + lane);
    for (int rr = 0; rr < 16; ++rr) {
        int r = rr * 8 + wid;
        int w = bm + r;
        uint2 uo;
        if (w < M) {
            int start = g_row_start[w];
            int end   = g_row_start[w + 1];
            float dn = g_dinv[w];
            float ax, ay, az, aw;
            {
                uint2 u = __ldg((const uint2*)&g_f1h[(size_t)w * HID_C] + lane);
                float2 f0 = __half22float2(*(__half2*)&u.x);
                float2 f1 = __half22float2(*(__half2*)&u.y);
                ax = f0.x * dn; ay = f0.y * dn; az = f1.x * dn; aw = f1.y * dn;
            }
            int i = start;
            for (; i + 8 <= end; i += 8) {
                int   sv[8]; float dv[8]; uint2 uv[8];
                #pragma unroll
                for (int k = 0; k < 8; ++k) sv[k] = g_src[i + k];
                #pragma unroll
                for (int k = 0; k < 8; ++k) dv[k] = g_dinv[sv[k]];
                #pragma unroll
                for (int k = 0; k < 8; ++k)
                    uv[k] = __ldg((const uint2*)&g_f1h[(size_t)sv[k] * HID_C] + lane);
                #pragma unroll
                for (int k = 0; k < 8; ++k) {
                    float2 p = __half22float2(*(__half2*)&uv[k].x);
                    float2 q = __half22float2(*(__half2*)&uv[k].y);
                    ax += p.x * dv[k]; ay += p.y * dv[k];
                    az += q.x * dv[k]; aw += q.y * dv[k];
                }
            }
            for (; i + 4 <= end; i += 4) {
                int   sv[4]; float dv[4]; uint2 uv[4];
                #pragma unroll
                for (int k = 0; k < 4; ++k) sv[k] = g_src[i + k];
                #pragma unroll
                for (int k = 0; k < 4; ++k) dv[k] = g_dinv[sv[k]];
                #pragma unroll
                for (int k = 0; k < 4; ++k)
                    uv[k] = __ldg((const uint2*)&g_f1h[(size_t)sv[k] * HID_C] + lane);
                #pragma unroll
                for (int k = 0; k < 4; ++k) {
                    float2 p = __half22float2(*(__half2*)&uv[k].x);
                    float2 q = __half22float2(*(__half2*)&uv[k].y);
                    ax += p.x * dv[k]; ay += p.y * dv[k];
                    az += q.x * dv[k]; aw += q.y * dv[k];
                }
            }
            for (; i < end; ++i) {
                int s = g_src[i];
                float ds = g_dinv[s];
                uint2 u = __ldg((const uint2*)&g_f1h[(size_t)s * HID_C] + lane);
                float2 p = __half22float2(*(__half2*)&u.x);
                float2 q = __half22float2(*(__half2*)&u.y);
                ax += p.x * ds; ay += p.y * ds; az += q.x * ds; aw += q.y * ds;
            }
            __half2 h0 = __floats2half2_rn(fmaxf(fmaf(ax, dn, bb.x), 0.f),
                                           fmaxf(fmaf(ay, dn, bb.y), 0.f));
            __half2 h1 = __floats2half2_rn(fmaxf(fmaf(az, dn, bb.z), 0.f),
                                           fmaxf(fmaf(aw, dn, bb.w), 0.f));
            uo.x = *(uint32_t*)&h0; uo.y = *(uint32_t*)&h1;
        } else {
            uo.x = 0u; uo.y = 0u;
        }
        *(uint2*)&As[r * FPAD + lane * 4] = uo;
    }
    CP_WAIT0();
    __syncthreads();

    int wm = wid & 3;
    int wn = wid >> 2;
    wmma::fragment<wmma::accumulator, 16, 16, 16, float> c[2][2];
    #pragma unroll
    for (int i = 0; i < 2; i++)
        #pragma unroll
        for (int j = 0; j < 2; j++) wmma::fill_fragment(c[i][j], 0.f);
    #pragma unroll
    for (int ks = 0; ks < HID_C; ks += 16) {
        wmma::fragment<wmma::matrix_a, 16, 16, 16, __half, wmma::row_major> a[2];
        wmma::fragment<wmma::matrix_b, 16, 16, 16, __half, wmma::row_major> b[2];
        #pragma unroll
        for (int i = 0; i < 2; i++)
            wmma::load_matrix_sync(a[i], &As[(wm * 32 + i * 16) * FPAD + ks], FPAD);
        #pragma unroll
        for (int j = 0; j < 2; j++)
            wmma::load_matrix_sync(b[j], &Bsm[ks * BPAD + wn * 32 + j * 16], BPAD);
        #pragma unroll
        for (int i = 0; i < 2; i++)
            #pragma unroll
            for (int j = 0; j < 2; j++)
                wmma::mma_sync(c[i][j], a[i], b[j], c[i][j]);
    }
    __syncthreads();

    #pragma unroll
    for (int i = 0; i < 2; i++)
        #pragma unroll
        for (int j = 0; j < 2; j++)
            wmma::store_matrix_sync(&stage[(wm * 32 + i * 16) * 64 + wn * 32 + j * 16],
                                    c[i][j], 64, wmma::mem_row_major);
    __syncthreads();
    #pragma unroll
    for (int it = 0; it < 16; ++it) {
        int idx = tid + it * 256;
        int r  = idx >> 5;
        int cp = idx & 31;
        int gm = bm + r;
        if (gm < M) {
            float2 f = *(float2*)&stage[r * 64 + cp * 2];
            *(__half2*)&g_f2h[(size_t)gm * OUT_C + cp * 2] = __float22half2_rn(f);
        }
    }
}

// ---------------- gather layer 2 + bias (16 lanes per node) -----------------
__global__ __launch_bounds__(256) void gather2_kernel(
    float* __restrict__ out, const float* __restrict__ b2, int M) {
    int t    = blockIdx.x * blockDim.x + threadIdx.x;
    int n    = t >> 4;
    int lane = t & 15;
    if (n >= M) return;
    int start = g_row_start[n];
    int end   = g_row_start[n + 1];
    float dn = g_dinv[n];

    float ax, ay, az, aw;
    {
        uint2 u = __ldg((const uint2*)&g_f2h[(size_t)n * OUT_C] + lane);
        float2 f0 = __half22float2(*(__half2*)&u.x);
        float2 f1 = __half22float2(*(__half2*)&u.y);
        ax = f0.x * dn; ay = f0.y * dn; az = f1.x * dn; aw = f1.y * dn;
    }

    int i = start;
    for (; i + 8 <= end; i += 8) {
        int   sv[8]; float dv[8]; uint2 uv[8];
        #pragma unroll
        for (int k = 0; k < 8; ++k) sv[k] = g_src[i + k];
        #pragma unroll
        for (int k = 0; k < 8; ++k) dv[k] = g_dinv[sv[k]];
        #pragma unroll
        for (int k = 0; k < 8; ++k)
            uv[k] = __ldg((const uint2*)&g_f2h[(size_t)sv[k] * OUT_C] + lane);
        #pragma unroll
        for (int k = 0; k < 8; ++k) {
            float2 p = __half22float2(*(__half2*)&uv[k].x);
            float2 q = __half22float2(*(__half2*)&uv[k].y);
            ax += p.x * dv[k]; ay += p.y * dv[k];
            az += q.x * dv[k]; aw += q.y * dv[k];
        }
    }
    for (; i + 4 <= end; i += 4) {
        int   sv[4]; float dv[4]; uint2 uv[4];
        #pragma unroll
        for (int k = 0; k < 4; ++k) sv[k] = g_src[i + k];
        #pragma unroll
        for (int k = 0; k < 4; ++k) dv[k] = g_dinv[sv[k]];
        #pragma unroll
        for (int k = 0; k < 4; ++k)
            uv[k] = __ldg((const uint2*)&g_f2h[(size_t)sv[k] * OUT_C] + lane);
        #pragma unroll
        for (int k = 0; k < 4; ++k) {
            float2 p = __half22float2(*(__half2*)&uv[k].x);
            float2 q = __half22float2(*(__half2*)&uv[k].y);
            ax += p.x * dv[k]; ay += p.y * dv[k];
            az += q.x * dv[k]; aw += q.y * dv[k];
        }
    }
    for (; i < end; ++i) {
        int s = g_src[i];
        float ds = g_dinv[s];
        uint2 u = __ldg((const uint2*)&g_f2h[(size_t)s * OUT_C] + lane);
        float2 p = __half22float2(*(__half2*)&u.x);
        float2 q = __half22float2(*(__half2*)&u.y);
        ax += p.x * ds; ay += p.y * ds; az += q.x * ds; aw += q.y * ds;
    }
    float4 bb = __ldg((const float4*)b2 + lane);
    float4 r;
    r.x = ax * dn + bb.x; r.y = ay * dn + bb.y;
    r.z = az * dn + bb.z; r.w = aw * dn + bb.w;
    *((float4*)&out[(size_t)n * OUT_C] + lane) = r;
}

// ---------------- launch ----------------------------------------------------
extern "C" void kernel_launch(void* const* d_in, const int* in_sizes, int n_in,
                              void* d_out, int out_size) {
    const float* features = (const float*)d_in[0];
    const void*  edge_idx = d_in[1];
    const float* W1 = (const float*)d_in[2];
    const float* b1 = (const float*)d_in[3];
    const float* W2 = (const float*)d_in[4];
    const float* b2 = (const float*)d_in[5];
    float* out = (float*)d_out;

    int M = in_sizes[0] / IN_C;       // 50000
    int E = in_sizes[1] / 2;          // 800000

    int gblocks = (M + 127) / 128;    // 391

    // Fork: fused weight-convert + dtype-detect, then gemm1 on side stream.
    cudaEventRecord(g_ss.ev_fork, 0);
    cudaStreamWaitEvent(g_ss.s2, g_ss.ev_fork, 0);
    {
        int totalw = (IN_C * HID_C + HID_C * OUT_C) / 8;
        int cblocks = (totalw + 255) / 256 + 1;   // +1 detect block
        convert_w_kernel<<<cblocks, 256, 0, g_ss.s2>>>(
            W1, W2, (const long long*)edge_idx, E, M);
    }
    cudaEventRecord(g_ss.ev_det, g_ss.s2);
    gemm1_kernel<<<gblocks, 256, 0, g_ss.s2>>>(features, M);
    cudaEventRecord(g_ss.ev_join, g_ss.s2);

    // Main stream: zero deg/ticket/scan-state, then CSR build.
    cudaMemsetAsync(g_ss.zero_ptr, 0, ZN * sizeof(int), 0);
    cudaStreamWaitEvent(0, g_ss.ev_det, 0);
    int e4blocks = ((E + 3) / 4 + 255) / 256;
    count_deg_kernel<<<e4blocks, 256>>>(edge_idx, E);
    scan_kernel<<<SCAN_B, 256>>>(M, E);
    fill_kernel<<<e4blocks, 256>>>(edge_idx, E);

    // Join: fused gather1+gemm2 needs gemm1 output, CSR, and W2h.
    cudaStreamWaitEvent(0, g_ss.ev_join, 0);

    fused2_kernel<<<gblocks, 256, FUSED2_SMEM>>>(b1, M);

    long long t2 = (long long)M * 16;
    gather2_kernel<<<(unsigned)((t2 + 255) / 256), 256>>>(out, b2, M);
}

// round 15
// speedup vs baseline: 1.0395x; 1.0395x over previous
#include <cuda_runtime.h>
#include <cuda_fp16.h>
#include <mma.h>
#include <cstdint>

using namespace nvcuda;

#define NODES_MAX 50000
#define PAD_M     50176      // 392*128, pad for unguarded wmma stores
#define E_MAX     1000000
#define IN_C  256
#define HID_C 128
#define OUT_C 64

#define SCAN_B    196        // scan blocks: 196*256 = 50176 >= NODES_MAX
#define ZN        (NODES_MAX + 1 + SCAN_B)   // deg | ticket | scan state

#define FPAD 136             // fused2 A smem row stride (halves)
#define BPAD 72              // fused2 B smem row stride (halves)
#define FUSED2_SMEM (128 * FPAD * 2 + 128 * BPAD * 2)   // 53248 bytes

// ---------------- scratch ----------------------------------------------------
__device__ __half g_w1h[IN_C * HID_C];       // W1, fp16
__device__ __half g_w2h[HID_C * OUT_C];      // W2, fp16
__device__ __half g_f1h[PAD_M * HID_C];      // gemm1 output (X@W1), fp16 messages
__device__ __half g_f2h[PAD_M * OUT_C];      // fused2 output, fp16 messages
__device__ float  g_dinv[NODES_MAX];
__device__ int    g_zero[ZN];                // [0,M)=deg, [NODES_MAX]=ticket,
                                             // [NODES_MAX+1,+SCAN_B)=scan state
__device__ int    g_row_start[NODES_MAX + 1];
__device__ int    g_cursor[NODES_MAX];
__device__ int    g_src[E_MAX];              // CSR-by-dst: source node per slot
__device__ int    g_is64;

__global__ void fused2_kernel(const float* __restrict__ b1, int M);

// ---------------- side stream / events / symbol addr (static init) ----------
namespace {
struct SideStream {
    cudaStream_t s2 = nullptr;
    cudaEvent_t  ev_fork = nullptr, ev_det = nullptr, ev_join = nullptr;
    void* zero_ptr = nullptr;
    SideStream() {
        cudaStreamCreateWithFlags(&s2, cudaStreamNonBlocking);
        cudaEventCreateWithFlags(&ev_fork, cudaEventDisableTiming);
        cudaEventCreateWithFlags(&ev_det,  cudaEventDisableTiming);
        cudaEventCreateWithFlags(&ev_join, cudaEventDisableTiming);
        cudaGetSymbolAddress(&zero_ptr, g_zero);
        cudaFuncSetAttribute(fused2_kernel,
                             cudaFuncAttributeMaxDynamicSharedMemorySize,
                             FUSED2_SMEM);
    }
};
SideStream g_ss;
}

// ---------------- cp.async helpers ------------------------------------------
__device__ __forceinline__ void cp16(void* smem, const void* gsrc, int szbytes) {
    uint32_t sa = (uint32_t)__cvta_generic_to_shared(smem);
    asm volatile("cp.async.cg.shared.global [%0], [%1], 16, %2;"
                 :: "r"(sa), "l"(gsrc), "r"(szbytes));
}
#define CP_COMMIT()  asm volatile("cp.async.commit_group;" ::: "memory")
#define CP_WAIT0()   asm volatile("cp.async.wait_group 0;" ::: "memory")

// ---------------- weight convert + dtype detect (fused, side stream) --------
__global__ __launch_bounds__(256) void convert_w_kernel(
    const float* __restrict__ W1, const float* __restrict__ W2,
    const long long* __restrict__ ei, int E, int M) {
    if ((int)blockIdx.x == (int)gridDim.x - 1) {
        __shared__ int bad;
        if (threadIdx.x == 0) bad = 0;
        __syncthreads();
        if ((int)threadIdx.x < E) {
            long long v = ei[threadIdx.x];
            if (v < 0 || v >= (long long)M) bad = 1;
        }
        __syncthreads();
        if (threadIdx.x == 0) g_is64 = bad ? 0 : 1;
        return;
    }
    int i = blockIdx.x * blockDim.x + threadIdx.x;
    int nw1 = IN_C * HID_C / 8;
    int nw2 = HID_C * OUT_C / 8;
    const float* src; __half* dst; int base;
    if (i < nw1)            { src = W1; dst = g_w1h; base = i; }
    else if (i < nw1 + nw2) { src = W2; dst = g_w2h; base = i - nw1; }
    else return;
    float4 a = ((const float4*)src)[base * 2];
    float4 b = ((const float4*)src)[base * 2 + 1];
    __half2 h0 = __floats2half2_rn(a.x, a.y);
    __half2 h1 = __floats2half2_rn(a.z, a.w);
    __half2 h2 = __floats2half2_rn(b.x, b.y);
    __half2 h3 = __floats2half2_rn(b.z, b.w);
    uint4 u;
    u.x = *(uint32_t*)&h0; u.y = *(uint32_t*)&h1;
    u.z = *(uint32_t*)&h2; u.w = *(uint32_t*)&h3;
    ((uint4*)dst)[base] = u;
}

// ---------------- edge loaders (4 edges/thread, vectorized) -----------------
__device__ __forceinline__ void load_dst4(const void* ei, int E, int e0, int is64,
                                          int n, int (&d)[4]) {
    if (is64) {
        const long long* p = (const long long*)ei + E + e0;
        if (n == 4) {
            longlong2 a = *(const longlong2*)p;
            longlong2 b = *(const longlong2*)(p + 2);
            d[0] = (int)a.x; d[1] = (int)a.y; d[2] = (int)b.x; d[3] = (int)b.y;
        } else {
            for (int k = 0; k < n; ++k) d[k] = (int)p[k];
        }
    } else {
        const int* p = (const int*)ei + E + e0;
        if (n == 4) {
            int4 a = *(const int4*)p;
            d[0] = a.x; d[1] = a.y; d[2] = a.z; d[3] = a.w;
        } else {
            for (int k = 0; k < n; ++k) d[k] = p[k];
        }
    }
}

__device__ __forceinline__ void load_src4(const void* ei, int e0, int is64,
                                          int n, int (&s)[4]) {
    if (is64) {
        const long long* p = (const long long*)ei + e0;
        if (n == 4) {
            longlong2 a = *(const longlong2*)p;
            longlong2 b = *(const longlong2*)(p + 2);
            s[0] = (int)a.x; s[1] = (int)a.y; s[2] = (int)b.x; s[3] = (int)b.y;
        } else {
            for (int k = 0; k < n; ++k) s[k] = (int)p[k];
        }
    } else {
        const int* p = (const int*)ei + e0;
        if (n == 4) {
            int4 a = *(const int4*)p;
            s[0] = a.x; s[1] = a.y; s[2] = a.z; s[3] = a.w;
        } else {
            for (int k = 0; k < n; ++k) s[k] = p[k];
        }
    }
}

// dst-only degree count, 4 edges/thread
__global__ void count_deg_kernel(const void* __restrict__ ei, int E) {
    int e0 = (blockIdx.x * blockDim.x + threadIdx.x) * 4;
    if (e0 >= E) return;
    int n = min(4, E - e0);
    int d[4];
    load_dst4(ei, E, e0, g_is64, n, d);
    #pragma unroll
    for (int k = 0; k < 4; ++k)
        if (k < n) atomicAdd(&g_zero[d[k]], 1);
}

// ---------------- single-kernel scan, warp-parallel lookback ----------------
__global__ __launch_bounds__(256) void scan_kernel(int M, int E) {
    __shared__ int bid_s;
    __shared__ int wsum[8];
    __shared__ int base_s;
    int t = threadIdx.x;
    if (t == 0) bid_s = atomicAdd(&g_zero[NODES_MAX], 1);
    __syncthreads();
    int bid = bid_s;
    int i = bid * 256 + t;
    int d = (i < M) ? g_zero[i] : 0;
    if (i < M) g_dinv[i] = rsqrtf((float)(d + 1));   // +1 self loop

    int lane = t & 31, wid = t >> 5;
    int v = d;
    #pragma unroll
    for (int off = 1; off < 32; off <<= 1) {
        int u = __shfl_up_sync(0xffffffffu, v, off);
        if (lane >= off) v += u;
    }
    if (lane == 31) wsum[wid] = v;
    __syncthreads();
    if (t < 8) {
        int s = wsum[t];
        #pragma unroll
        for (int off = 1; off < 8; off <<= 1) {
            int u = __shfl_up_sync(0xffu, s, off);
            if ((int)t >= off) s += u;
        }
        wsum[t] = s;
    }
    __syncthreads();
    int incl  = v + ((wid > 0) ? wsum[wid - 1] : 0);
    int total = wsum[7];

    int* state = &g_zero[NODES_MAX + 1];
    if (wid == 0) {
        if (bid == 0) {
            if (lane == 0) {
                atomicExch(&state[0], (int)((2u << 30) | (unsigned)total));
                base_s = 0;
            }
        } else {
            if (lane == 0)
                atomicExch(&state[bid], (int)((1u << 30) | (unsigned)total));
            int run = 0;
            int wstart = bid - 1;
            for (;;) {
                int j = wstart - lane;
                bool active = (j >= 0);
                unsigned s = 0;
                do {
                    if (active) s = (unsigned)atomicAdd(&state[j], 0);
                } while (__any_sync(0xffffffffu, active && (s >> 30) == 0u));
                unsigned incl_mask =
                    __ballot_sync(0xffffffffu, active && (s >> 30) == 2u);
                if (incl_mask) {
                    int L = __ffs(incl_mask) - 1;
                    int contrib = (active && lane <= L) ? (int)(s & 0x3FFFFFFFu) : 0;
                    run += __reduce_add_sync(0xffffffffu, contrib);
                    break;
                } else {
                    int contrib = active ? (int)(s & 0x3FFFFFFFu) : 0;
                    run += __reduce_add_sync(0xffffffffu, contrib);
                    wstart -= 32;
                    if (wstart < 0) break;
                }
            }
            if (lane == 0) {
                base_s = run;
                atomicExch(&state[bid], (int)((2u << 30) | (unsigned)(run + total)));
            }
        }
    }
    __syncthreads();
    int rs = base_s + incl - d;
    if (i < M) {
        g_row_start[i] = rs;
        g_cursor[i]    = rs;
    }
    if (i == M - 1) g_row_start[M] = E;
}

// CSR fill, 4 edges/thread
__global__ void fill_kernel(const void* __restrict__ ei, int E) {
    int e0 = (blockIdx.x * blockDim.x + threadIdx.x) * 4;
    if (e0 >= E) return;
    int n = min(4, E - e0);
    int s[4], d[4];
    load_src4(ei, e0, g_is64, n, s);
    load_dst4(ei, E, e0, g_is64, n, d);
    #pragma unroll
    for (int k = 0; k < 4; ++k) {
        if (k < n) {
            int pos = atomicAdd(&g_cursor[d[k]], 1);
            g_src[pos] = s[k];
        }
    }
}

// ---------------- GEMM1 (fp16 HMMA, inline X conversion): f1h = fp16(X)@W1h -
#define NT1 (IN_C / 32)
__global__ __launch_bounds__(256, 2) void gemm1_kernel(
    const float* __restrict__ X, int M) {
    __shared__ union {
        struct { __half As[2][128][40]; __half Bs[2][32][136]; } p;
        float stage[128 * 64];
    } sm;
    int tid = threadIdx.x;
    int wid = tid >> 5;
    int wm = wid & 3;
    int wn = wid >> 2;
    int bm = blockIdx.x * 128;

    wmma::fragment<wmma::accumulator, 16, 16, 16, float> c[2][4];
    #pragma unroll
    for (int i = 0; i < 2; i++)
        #pragma unroll
        for (int j = 0; j < 4; j++) wmma::fill_fragment(c[i][j], 0.f);

    float4 rg[4];
    auto ldA = [&](int kt) {
        int k0 = kt * 32;
        #pragma unroll
        for (int i = 0; i < 4; ++i) {
            int idx = tid * 4 + i;
            int r = idx >> 3, c4 = (idx & 7) * 4;
            int gm = bm + r;
            rg[i] = make_float4(0.f, 0.f, 0.f, 0.f);
            if (gm < M) rg[i] = *(const float4*)&X[(size_t)gm * IN_C + k0 + c4];
        }
    };
    auto stA = [&](int buf) {
        #pragma unroll
        for (int i = 0; i < 4; ++i) {
            int idx = tid * 4 + i;
            int r = idx >> 3, c4 = (idx & 7) * 4;
            __half2 h0 = __floats2half2_rn(rg[i].x, rg[i].y);
            __half2 h1 = __floats2half2_rn(rg[i].z, rg[i].w);
            uint2 u;
            u.x = *(uint32_t*)&h0; u.y = *(uint32_t*)&h1;
            *(uint2*)&sm.p.As[buf][r][c4] = u;
        }
    };
    auto issueB = [&](int kt, int buf) {
        int k0 = kt * 32;
        #pragma unroll
        for (int i = 0; i < 2; ++i) {
            int idx = tid * 2 + i;
            int kk = idx >> 4, n8 = (idx & 15) * 8;
            cp16(&sm.p.Bs[buf][kk][n8], &g_w1h[(size_t)(k0 + kk) * HID_C + n8], 16);
        }
        CP_COMMIT();
    };
    auto compute = [&](int buf) {
        #pragma unroll
        for (int ks = 0; ks < 32; ks += 16) {
            wmma::fragment<wmma::matrix_a, 16, 16, 16, __half, wmma::row_major> a[2];
            wmma::fragment<wmma::matrix_b, 16, 16, 16, __half, wmma::row_major> b[4];
            #pragma unroll
            for (int i = 0; i < 2; i++)
                wmma::load_matrix_sync(a[i], &sm.p.As[buf][wm * 32 + i * 16][ks], 40);
            #pragma unroll
            for (int j = 0; j < 4; j++)
                wmma::load_matrix_sync(b[j], &sm.p.Bs[buf][ks][wn * 64 + j * 16], 136);
            #pragma unroll
            for (int i = 0; i < 2; i++)
                #pragma unroll
                for (int j = 0; j < 4; j++)
                    wmma::mma_sync(c[i][j], a[i], b[j], c[i][j]);
        }
    };

    ldA(0); issueB(0, 0);
    stA(0); CP_WAIT0(); __syncthreads();
    for (int t = 0; t < NT1; ++t) {
        bool more = (t + 1 < NT1);
        if (more) { ldA(t + 1); issueB(t + 1, (t + 1) & 1); }
        compute(t & 1);
        if (more) { stA((t + 1) & 1); CP_WAIT0(); }
        __syncthreads();
    }

    #pragma unroll
    for (int half = 0; half < 2; ++half) {
        if (wn == half) {
            #pragma unroll
            for (int i = 0; i < 2; i++)
                #pragma unroll
                for (int j = 0; j < 4; j++)
                    wmma::store_matrix_sync(&sm.stage[(wm * 32 + i * 16) * 64 + j * 16],
                                            c[i][j], 64, wmma::mem_row_major);
        }
        __syncthreads();
        #pragma unroll
        for (int it = 0; it < 16; ++it) {
            int idx = tid + it * 256;
            int r  = idx >> 5;
            int cp = idx & 31;
            int gm = bm + r;
            if (gm < M) {
                float2 f = *(float2*)&sm.stage[r * 64 + cp * 2];
                *(__half2*)&g_f1h[(size_t)gm * HID_C + half * 64 + cp * 2] =
                    __float22half2_rn(f);
            }
        }
        __syncthreads();
    }
}

// ---------------- FUSED: gather1 (+b1, relu) -> smem -> GEMM2 -> f2h --------
// 512 threads (16 warps): 8 nodes/warp gather, 4x4 warp-grid GEMM. 3 CTA/SM.
__global__ __launch_bounds__(512, 3) void fused2_kernel(const float* __restrict__ b1, int M) {
    extern __shared__ char dyn_sm[];
    __half* As   = (__half*)dyn_sm;                       // [128][FPAD]
    __half* Bsm  = (__half*)(dyn_sm + 128 * FPAD * 2);    // [128][BPAD]
    float*  stage = (float*)dyn_sm;                       // overlaps As (after GEMM)

    int tid  = threadIdx.x;
    int wid  = tid >> 5;      // 0..15
    int lane = tid & 31;
    int bm   = blockIdx.x * 128;

    // Prefetch full W2 (128x64 fp16): 1024 chunks of 16B, 512 threads x 2.
    #pragma unroll
    for (int i = 0; i < 2; ++i) {
        int cidx = tid + i * 512;
        int row  = cidx >> 3;
        int off8 = (cidx & 7) * 8;
        cp16(&Bsm[row * BPAD + off8], &g_w2h[row * OUT_C + off8], 16);
    }
    CP_COMMIT();

    // Gather phase: each warp handles 8 rows (r = rr*16 + wid).
    float4 bb = __ldg((const float4*)b1 + lane);
    for (int rr = 0; rr < 8; ++rr) {
        int r = rr * 16 + wid;
        int w = bm + r;
        uint2 uo;
        if (w < M) {
            int start = g_row_start[w];
            int end   = g_row_start[w + 1];
            float dn = g_dinv[w];
            float ax, ay, az, aw;
            {
                uint2 u = __ldg((const uint2*)&g_f1h[(size_t)w * HID_C] + lane);
                float2 f0 = __half22float2(*(__half2*)&u.x);
                float2 f1 = __half22float2(*(__half2*)&u.y);
                ax = f0.x * dn; ay = f0.y * dn; az = f1.x * dn; aw = f1.y * dn;
            }
            int i = start;
            for (; i + 8 <= end; i += 8) {
                int   sv[8]; float dv[8]; uint2 uv[8];
                #pragma unroll
                for (int k = 0; k < 8; ++k) sv[k] = g_src[i + k];
                #pragma unroll
                for (int k = 0; k < 8; ++k) dv[k] = g_dinv[sv[k]];
                #pragma unroll
                for (int k = 0; k < 8; ++k)
                    uv[k] = __ldg((const uint2*)&g_f1h[(size_t)sv[k] * HID_C] + lane);
                #pragma unroll
                for (int k = 0; k < 8; ++k) {
                    float2 p = __half22float2(*(__half2*)&uv[k].x);
                    float2 q = __half22float2(*(__half2*)&uv[k].y);
                    ax += p.x * dv[k]; ay += p.y * dv[k];
                    az += q.x * dv[k]; aw += q.y * dv[k];
                }
            }
            for (; i + 4 <= end; i += 4) {
                int   sv[4]; float dv[4]; uint2 uv[4];
                #pragma unroll
                for (int k = 0; k < 4; ++k) sv[k] = g_src[i + k];
                #pragma unroll
                for (int k = 0; k < 4; ++k) dv[k] = g_dinv[sv[k]];
                #pragma unroll
                for (int k = 0; k < 4; ++k)
                    uv[k] = __ldg((const uint2*)&g_f1h[(size_t)sv[k] * HID_C] + lane);
                #pragma unroll
                for (int k = 0; k < 4; ++k) {
                    float2 p = __half22float2(*(__half2*)&uv[k].x);
                    float2 q = __half22float2(*(__half2*)&uv[k].y);
                    ax += p.x * dv[k]; ay += p.y * dv[k];
                    az += q.x * dv[k]; aw += q.y * dv[k];
                }
            }
            for (; i < end; ++i) {
                int s = g_src[i];
                float ds = g_dinv[s];
                uint2 u = __ldg((const uint2*)&g_f1h[(size_t)s * HID_C] + lane);
                float2 p = __half22float2(*(__half2*)&u.x);
                float2 q = __half22float2(*(__half2*)&u.y);
                ax += p.x * ds; ay += p.y * ds; az += q.x * ds; aw += q.y * ds;
            }
            __half2 h0 = __floats2half2_rn(fmaxf(fmaf(ax, dn, bb.x), 0.f),
                                           fmaxf(fmaf(ay, dn, bb.y), 0.f));
            __half2 h1 = __floats2half2_rn(fmaxf(fmaf(az, dn, bb.z), 0.f),
                                           fmaxf(fmaf(aw, dn, bb.w), 0.f));
            uo.x = *(uint32_t*)&h0; uo.y = *(uint32_t*)&h1;
        } else {
            uo.x = 0u; uo.y = 0u;
        }
        *(uint2*)&As[r * FPAD + lane * 4] = uo;
    }
    CP_WAIT0();
    __syncthreads();

    // GEMM phase: 128x64x128, 16 warps, warp tile 32x16 (wm 0..3, wn 0..3).
    int wm = wid & 3;
    int wn = wid >> 2;
    wmma::fragment<wmma::accumulator, 16, 16, 16, float> c[2];
    #pragma unroll
    for (int i = 0; i < 2; i++) wmma::fill_fragment(c[i], 0.f);
    #pragma unroll
    for (int ks = 0; ks < HID_C; ks += 16) {
        wmma::fragment<wmma::matrix_a, 16, 16, 16, __half, wmma::row_major> a[2];
        wmma::fragment<wmma::matrix_b, 16, 16, 16, __half, wmma::row_major> b;
        #pragma unroll
        for (int i = 0; i < 2; i++)
            wmma::load_matrix_sync(a[i], &As[(wm * 32 + i * 16) * FPAD + ks], FPAD);
        wmma::load_matrix_sync(b, &Bsm[ks * BPAD + wn * 16], BPAD);
        #pragma unroll
        for (int i = 0; i < 2; i++)
            wmma::mma_sync(c[i], a[i], b, c[i]);
    }
    __syncthreads();   // As dead; stage overlaps it

    #pragma unroll
    for (int i = 0; i < 2; i++)
        wmma::store_matrix_sync(&stage[(wm * 32 + i * 16) * 64 + wn * 16],
                                c[i], 64, wmma::mem_row_major);
    __syncthreads();
    #pragma unroll
    for (int it = 0; it < 8; ++it) {
        int idx = tid + it * 512;     // 0..4095 half2 slots (128 rows x 32)
        int r  = idx >> 5;
        int cp = idx & 31;
        int gm = bm + r;
        if (gm < M) {
            float2 f = *(float2*)&stage[r * 64 + cp * 2];
            *(__half2*)&g_f2h[(size_t)gm * OUT_C + cp * 2] = __float22half2_rn(f);
        }
    }
}

// ---------------- gather layer 2 + bias (16 lanes per node) -----------------
__global__ __launch_bounds__(256) void gather2_kernel(
    float* __restrict__ out, const float* __restrict__ b2, int M) {
    int t    = blockIdx.x * blockDim.x + threadIdx.x;
    int n    = t >> 4;
    int lane = t & 15;
    if (n >= M) return;
    int start = g_row_start[n];
    int end   = g_row_start[n + 1];
    float dn = g_dinv[n];

    float ax, ay, az, aw;
    {
        uint2 u = __ldg((const uint2*)&g_f2h[(size_t)n * OUT_C] + lane);
        float2 f0 = __half22float2(*(__half2*)&u.x);
        float2 f1 = __half22float2(*(__half2*)&u.y);
        ax = f0.x * dn; ay = f0.y * dn; az = f1.x * dn; aw = f1.y * dn;
    }

    int i = start;
    for (; i + 8 <= end; i += 8) {
        int   sv[8]; float dv[8]; uint2 uv[8];
        #pragma unroll
        for (int k = 0; k < 8; ++k) sv[k] = g_src[i + k];
        #pragma unroll
        for (int k = 0; k < 8; ++k) dv[k] = g_dinv[sv[k]];
        #pragma unroll
        for (int k = 0; k < 8; ++k)
            uv[k] = __ldg((const uint2*)&g_f2h[(size_t)sv[k] * OUT_C] + lane);
        #pragma unroll
        for (int k = 0; k < 8; ++k) {
            float2 p = __half22float2(*(__half2*)&uv[k].x);
            float2 q = __half22float2(*(__half2*)&uv[k].y);
            ax += p.x * dv[k]; ay += p.y * dv[k];
            az += q.x * dv[k]; aw += q.y * dv[k];
        }
    }
    for (; i + 4 <= end; i += 4) {
        int   sv[4]; float dv[4]; uint2 uv[4];
        #pragma unroll
        for (int k = 0; k < 4; ++k) sv[k] = g_src[i + k];
        #pragma unroll
        for (int k = 0; k < 4; ++k) dv[k] = g_dinv[sv[k]];
        #pragma unroll
        for (int k = 0; k < 4; ++k)
            uv[k] = __ldg((const uint2*)&g_f2h[(size_t)sv[k] * OUT_C] + lane);
        #pragma unroll
        for (int k = 0; k < 4; ++k) {
            float2 p = __half22float2(*(__half2*)&uv[k].x);
            float2 q = __half22float2(*(__half2*)&uv[k].y);
            ax += p.x * dv[k]; ay += p.y * dv[k];
            az += q.x * dv[k]; aw += q.y * dv[k];
        }
    }
    for (; i < end; ++i) {
        int s = g_src[i];
        float ds = g_dinv[s];
        uint2 u = __ldg((const uint2*)&g_f2h[(size_t)s * OUT_C] + lane);
        float2 p = __half22float2(*(__half2*)&u.x);
        float2 q = __half22float2(*(__half2*)&u.y);
        ax += p.x * ds; ay += p.y * ds; az += q.x * ds; aw += q.y * ds;
    }
    float4 bb = __ldg((const float4*)b2 + lane);
    float4 r;
    r.x = ax * dn + bb.x; r.y = ay * dn + bb.y;
    r.z = az * dn + bb.z; r.w = aw * dn + bb.w;
    *((float4*)&out[(size_t)n * OUT_C] + lane) = r;
}

// ---------------- launch ----------------------------------------------------
extern "C" void kernel_launch(void* const* d_in, const int* in_sizes, int n_in,
                              void* d_out, int out_size) {
    const float* features = (const float*)d_in[0];
    const void*  edge_idx = d_in[1];
    const float* W1 = (const float*)d_in[2];
    const float* b1 = (const float*)d_in[3];
    const float* W2 = (const float*)d_in[4];
    const float* b2 = (const float*)d_in[5];
    float* out = (float*)d_out;

    int M = in_sizes[0] / IN_C;       // 50000
    int E = in_sizes[1] / 2;          // 800000

    int gblocks = (M + 127) / 128;    // 391

    // Fork: fused weight-convert + dtype-detect, then gemm1 on side stream.
    cudaEventRecord(g_ss.ev_fork, 0);
    cudaStreamWaitEvent(g_ss.s2, g_ss.ev_fork, 0);
    {
        int totalw = (IN_C * HID_C + HID_C * OUT_C) / 8;
        int cblocks = (totalw + 255) / 256 + 1;   // +1 detect block
        convert_w_kernel<<<cblocks, 256, 0, g_ss.s2>>>(
            W1, W2, (const long long*)edge_idx, E, M);
    }
    cudaEventRecord(g_ss.ev_det, g_ss.s2);
    gemm1_kernel<<<gblocks, 256, 0, g_ss.s2>>>(features, M);
    cudaEventRecord(g_ss.ev_join, g_ss.s2);

    // Main stream: zero deg/ticket/scan-state, then CSR build.
    cudaMemsetAsync(g_ss.zero_ptr, 0, ZN * sizeof(int), 0);
    cudaStreamWaitEvent(0, g_ss.ev_det, 0);
    int e4blocks = ((E + 3) / 4 + 255) / 256;
    count_deg_kernel<<<e4blocks, 256>>>(edge_idx, E);
    scan_kernel<<<SCAN_B, 256>>>(M, E);
    fill_kernel<<<e4blocks, 256>>>(edge_idx, E);

    // Join: fused gather1+gemm2 needs gemm1 output, CSR, and W2h.
    cudaStreamWaitEvent(0, g_ss.ev_join, 0);

    fused2_kernel<<<gblocks, 512, FUSED2_SMEM>>>(b1, M);

    long long t2 = (long long)M * 16;
    gather2_kernel<<<(unsigned)((t2 + 255) / 256), 256>>>(out, b2, M);
}